// round 16
// baseline (speedup 1.0000x reference)
#include <cuda_runtime.h>
#include <math.h>
#include <stdint.h>

#define BB 4
#define TT 4096
#define DD 1024
#define NO 256      // 2*dv
#define NROW (BB*TT)
#define LN_EPS_F 1e-5f
#define LAMBDA_INIT 0.3555090675909693f
#define ATT_SCALE 0.0883883476483184405f   // 1/sqrt(128)

typedef unsigned long long u64;

// packed f32x2 helpers (sm_100+ PTX; SASS FFMA2/FADD2)
#define FFMA2(d, a, b) asm("fma.rn.f32x2 %0, %1, %2, %0;" : "+l"(d) : "l"(a), "l"(b))
#define PACK2(d, x)    asm("mov.b64 %0, {%1, %1};" : "=l"(d) : "r"(__float_as_uint(x)))
#define UNPACK2(lo, hi, v) do { unsigned _ul, _uh; \
    asm("mov.b64 {%0, %1}, %2;" : "=r"(_ul), "=r"(_uh) : "l"(v)); \
    (lo) = __uint_as_float(_ul); (hi) = __uint_as_float(_uh); } while (0)

// scratch (device globals: allocation-free rule)
__device__ float g_Q[NROW * NO];
__device__ float g_K[NROW * NO];
__device__ float g_V[NROW * NO];
__device__ float g_P1[67108864];     // [NROW][TT] exp-scores head 1
__device__ float g_P2[67108864];     // [NROW][TT] exp-scores head 2
__device__ float g_Lp[NROW * 64];    // per-(row, keytile, head) partial sums
__device__ float g_Winv[NROW * 2];   // (1/l1, lambda/l2) per row
__device__ float g_lambda;

// ---------------------------------------------------------------------------
// Kernel 1: QKV GEMM, smem double-buffer + PRE-DUPLICATED W operand
// (no PACK2 in inner loop).  BM=BN=128, BK=16, dynamic smem.
// Layout (floats): Xs[2][16][132] @0 ; Wsd[2][16][260] @4224 (dup W rows)
// ---------------------------------------------------------------------------
#define QKV_SMEM ((4224 + 8320) * 4)
__global__ __launch_bounds__(256) void qkv_gemm(
    const float* __restrict__ x,
    const float* __restrict__ Wq,
    const float* __restrict__ Wk,
    const float* __restrict__ Wv)
{
    extern __shared__ float smq[];
#define XS(bf, k, r)  smq[(bf) * 2112 + (k) * 132 + (r)]
#define WSD(bf, k, p) smq[4224 + (bf) * 4160 + (k) * 260 + (p)]

    const int nt  = blockIdx.x;
    const int mt  = blockIdx.y;
    const int mat = nt >> 1;
    const int n0  = (nt & 1) * 128;
    const float* W = (mat == 0) ? Wq : ((mat == 1) ? Wk : Wv);
    float* Out     = (mat == 0) ? g_Q : ((mat == 1) ? g_K : g_V);

    const int m0  = mt * 128;
    const int tid = threadIdx.x;
    const int tx  = tid & 15;
    const int ty  = tid >> 4;

    const int xrow = tid >> 2;
    const int xkc  = tid & 3;
    const int wkr  = tid >> 5;
    const int wnc  = tid & 31;

    const float* xp0 = x + (size_t)(m0 + xrow) * DD + xkc * 4;
    const float* xp1 = x + (size_t)(m0 + xrow + 64) * DD + xkc * 4;
    const float* wp0 = W + (size_t)wkr * NO + n0 + wnc * 4;
    const float* wp1 = W + (size_t)(wkr + 8) * NO + n0 + wnc * 4;

    u64 c[4][8];
#pragma unroll
    for (int i = 0; i < 4; i++)
#pragma unroll
        for (int j = 0; j < 8; j++) c[i][j] = 0ull;

    float4 xr0 = *(const float4*)xp0;
    float4 xr1 = *(const float4*)xp1;
    float4 wr0 = *(const float4*)wp0;
    float4 wr1 = *(const float4*)wp1;

    for (int it = 0; it < 64; it++) {
        const int bf = it & 1;
        XS(bf, xkc * 4 + 0, xrow)      = xr0.x;
        XS(bf, xkc * 4 + 1, xrow)      = xr0.y;
        XS(bf, xkc * 4 + 2, xrow)      = xr0.z;
        XS(bf, xkc * 4 + 3, xrow)      = xr0.w;
        XS(bf, xkc * 4 + 0, xrow + 64) = xr1.x;
        XS(bf, xkc * 4 + 1, xrow + 64) = xr1.y;
        XS(bf, xkc * 4 + 2, xrow + 64) = xr1.z;
        XS(bf, xkc * 4 + 3, xrow + 64) = xr1.w;
        {   // duplicated W stores: {v,v} u64 pairs
            u64 d0, d1, d2, d3;
            PACK2(d0, wr0.x); PACK2(d1, wr0.y); PACK2(d2, wr0.z); PACK2(d3, wr0.w);
            *(ulonglong2*)(&WSD(bf, wkr, 8 * wnc))     = make_ulonglong2(d0, d1);
            *(ulonglong2*)(&WSD(bf, wkr, 8 * wnc + 4)) = make_ulonglong2(d2, d3);
            PACK2(d0, wr1.x); PACK2(d1, wr1.y); PACK2(d2, wr1.z); PACK2(d3, wr1.w);
            *(ulonglong2*)(&WSD(bf, wkr + 8, 8 * wnc))     = make_ulonglong2(d0, d1);
            *(ulonglong2*)(&WSD(bf, wkr + 8, 8 * wnc + 4)) = make_ulonglong2(d2, d3);
        }
        __syncthreads();

        if (it < 63) {
            const int k0 = (it + 1) * 16;
            xr0 = *(const float4*)(xp0 + k0);
            xr1 = *(const float4*)(xp1 + k0);
            wr0 = *(const float4*)(wp0 + (size_t)k0 * NO);
            wr1 = *(const float4*)(wp1 + (size_t)k0 * NO);
        }

#pragma unroll
        for (int kk = 0; kk < 16; kk++) {
            ulonglong2 A0 = *(const ulonglong2*)(&XS(bf, kk, ty * 4));
            ulonglong2 A1 = *(const ulonglong2*)(&XS(bf, kk, 64 + ty * 4));
            ulonglong2 wl0 = *(const ulonglong2*)(&WSD(bf, kk, 8 * tx));
            ulonglong2 wl1 = *(const ulonglong2*)(&WSD(bf, kk, 8 * tx + 4));
            ulonglong2 wh0 = *(const ulonglong2*)(&WSD(bf, kk, 128 + 8 * tx));
            ulonglong2 wh1 = *(const ulonglong2*)(&WSD(bf, kk, 128 + 8 * tx + 4));
            u64 B[8] = {wl0.x, wl0.y, wl1.x, wl1.y, wh0.x, wh0.y, wh1.x, wh1.y};
#pragma unroll
            for (int j = 0; j < 8; j++) {
                FFMA2(c[0][j], A0.x, B[j]);
                FFMA2(c[1][j], A0.y, B[j]);
                FFMA2(c[2][j], A1.x, B[j]);
                FFMA2(c[3][j], A1.y, B[j]);
            }
        }
    }

#pragma unroll
    for (int rp = 0; rp < 4; rp++) {
        const int r = (rp < 2) ? (ty * 4 + rp * 2) : (64 + ty * 4 + (rp - 2) * 2);
        float lo[8], hi[8];
#pragma unroll
        for (int j = 0; j < 8; j++) UNPACK2(lo[j], hi[j], c[rp][j]);
        float* o0 = Out + (size_t)(m0 + r) * NO + n0;
        float* o1 = o0 + NO;
        *(float4*)(o0 + tx * 4)      = make_float4(lo[0], lo[1], lo[2], lo[3]);
        *(float4*)(o0 + 64 + tx * 4) = make_float4(lo[4], lo[5], lo[6], lo[7]);
        *(float4*)(o1 + tx * 4)      = make_float4(hi[0], hi[1], hi[2], hi[3]);
        *(float4*)(o1 + 64 + tx * 4) = make_float4(hi[4], hi[5], hi[6], hi[7]);
    }
#undef XS
#undef WSD
}

// ---------------------------------------------------------------------------
// Kernel 2: recompute the 64 state rows with the *_state weights.
// ---------------------------------------------------------------------------
__global__ __launch_bounds__(256) void state_fixup(
    const float* __restrict__ x,
    const float* __restrict__ Wqs,
    const float* __restrict__ Wks,
    const float* __restrict__ Wvs)
{
    __shared__ float xs[DD];
    const int id = blockIdx.x;
    const int b  = id >> 4;
    const int i  = id & 15;
    const int t  = (i < 8) ? i : (TT - 16 + i);
    const size_t row = (size_t)b * TT + t;
    const int tid = threadIdx.x;

    for (int d = tid; d < DD; d += 256) xs[d] = x[row * DD + d];
    __syncthreads();

    float aq = 0.f, ak = 0.f, av = 0.f;
    const int n = tid;
#pragma unroll 4
    for (int d = 0; d < DD; d++) {
        float xv = xs[d];
        aq += xv * Wqs[(size_t)d * NO + n];
        ak += xv * Wks[(size_t)d * NO + n];
        av += xv * Wvs[(size_t)d * NO + n];
    }
    g_Q[row * NO + n] = aq;
    g_K[row * NO + n] = ak;
    g_V[row * NO + n] = av;
}

// ---------------------------------------------------------------------------
// Kernel 3: lambda scalar
// ---------------------------------------------------------------------------
__global__ void lambda_kernel(const float* __restrict__ lq1,
                              const float* __restrict__ lq2,
                              const float* __restrict__ lk1,
                              const float* __restrict__ lk2)
{
    int lane = threadIdx.x;
    float s1 = 0.f, s2 = 0.f;
    for (int i = lane; i < 128; i += 32) {
        s1 += lq1[i] * lk1[i];
        s2 += lq2[i] * lk2[i];
    }
#pragma unroll
    for (int o = 16; o > 0; o >>= 1) {
        s1 += __shfl_xor_sync(0xffffffffu, s1, o);
        s2 += __shfl_xor_sync(0xffffffffu, s2, o);
    }
    if (lane == 0) g_lambda = expf(s1) - expf(s2) + LAMBDA_INIT;
}

// ---------------------------------------------------------------------------
// Kernel 4 (A): score GEMM, PRE-DUPLICATED K operand (no PACK2 inner loop),
// coalesced staging + reg prefetch + smem double-buffer, dynamic smem.
// Layout (floats): Qs[2][16][132] @0 ; Ksd[2][16][264] @4224.
// ---------------------------------------------------------------------------
#define SC_SMEM ((4224 + 8448) * 4)
__global__ __launch_bounds__(256, 2) void score_kernel()
{
    extern __shared__ float sms[];
#define QS(bf, k, r)  sms[(bf) * 2112 + (k) * 132 + (r)]
#define KSD(bf, k, p) sms[4224 + (bf) * 4224 + (k) * 264 + (p)]

    const int b = blockIdx.y;
    const int t = blockIdx.x;
    int r = (int)((sqrtf(8.f * t + 1.f) - 1.f) * 0.5f);
    while ((r + 1) * (r + 2) / 2 <= t) r++;
    while (r * (r + 1) / 2 > t) r--;
    const int kt  = t - r * (r + 1) / 2;
    const int r0g = r * 128;
    const int k0g = kt * 128;
    const size_t rowb = (size_t)b * TT;

    const int tid = threadIdx.x;
    const int tx  = tid & 15;
    const int ty  = tid >> 4;
    const int sdq = tid & 3;
    const int sr0 = tid >> 2;

    const float* qb0 = g_Q + (rowb + r0g + sr0) * NO + sdq * 4;
    const float* qb1 = qb0 + (size_t)64 * NO;
    const float* kb0 = g_K + (rowb + k0g + sr0) * NO + sdq * 4;
    const float* kb1 = kb0 + (size_t)64 * NO;

    float4 pq[2], pk[2];
#define SLOADG(g) do { \
        int db_ = (((g) >> 3) * 128) + (((g) & 7) * 16); \
        pq[0] = *(const float4*)(qb0 + db_); \
        pq[1] = *(const float4*)(qb1 + db_); \
        pk[0] = *(const float4*)(kb0 + db_); \
        pk[1] = *(const float4*)(kb1 + db_); \
    } while (0)

    u64 c[4][8];
#pragma unroll
    for (int i = 0; i < 4; i++)
#pragma unroll
        for (int j = 0; j < 8; j++) c[i][j] = 0ull;

    SLOADG(0);

    for (int g = 0; g < 16; g++) {
        const int bf = g & 1;
#pragma unroll
        for (int i = 0; i < 2; i++) {
            int row = sr0 + i * 64;
            QS(bf, sdq * 4 + 0, row) = pq[i].x * ATT_SCALE;
            QS(bf, sdq * 4 + 1, row) = pq[i].y * ATT_SCALE;
            QS(bf, sdq * 4 + 2, row) = pq[i].z * ATT_SCALE;
            QS(bf, sdq * 4 + 3, row) = pq[i].w * ATT_SCALE;
            u64 d0, d1, d2, d3;
            PACK2(d0, pk[i].x); PACK2(d1, pk[i].y);
            PACK2(d2, pk[i].z); PACK2(d3, pk[i].w);
            *(u64*)(&KSD(bf, sdq * 4 + 0, 2 * row)) = d0;
            *(u64*)(&KSD(bf, sdq * 4 + 1, 2 * row)) = d1;
            *(u64*)(&KSD(bf, sdq * 4 + 2, 2 * row)) = d2;
            *(u64*)(&KSD(bf, sdq * 4 + 3, 2 * row)) = d3;
        }
        __syncthreads();
        if (g < 15) SLOADG(g + 1);

#pragma unroll
        for (int kk = 0; kk < 16; kk++) {
            ulonglong2 A0 = *(const ulonglong2*)(&QS(bf, kk, ty * 4));
            ulonglong2 A1 = *(const ulonglong2*)(&QS(bf, kk, 64 + ty * 4));
            ulonglong2 kl0 = *(const ulonglong2*)(&KSD(bf, kk, 8 * tx));
            ulonglong2 kl1 = *(const ulonglong2*)(&KSD(bf, kk, 8 * tx + 4));
            ulonglong2 kh0 = *(const ulonglong2*)(&KSD(bf, kk, 128 + 8 * tx));
            ulonglong2 kh1 = *(const ulonglong2*)(&KSD(bf, kk, 128 + 8 * tx + 4));
            u64 B[8] = {kl0.x, kl0.y, kl1.x, kl1.y, kh0.x, kh0.y, kh1.x, kh1.y};
#pragma unroll
            for (int j = 0; j < 8; j++) {
                FFMA2(c[0][j], A0.x, B[j]);
                FFMA2(c[1][j], A0.y, B[j]);
                FFMA2(c[2][j], A1.x, B[j]);
                FFMA2(c[3][j], A1.y, B[j]);
            }
        }

        if ((g & 7) == 7) {
            const int ph = g >> 3;
            float* Pout = ph ? g_P2 : g_P1;
#pragma unroll
            for (int rp = 0; rp < 4; rp++) {
                const int rl = (rp < 2) ? (ty * 4 + rp * 2)
                                        : (64 + ty * 4 + (rp - 2) * 2);
                float lo[8], hi[8];
#pragma unroll
                for (int j = 0; j < 8; j++) UNPACK2(lo[j], hi[j], c[rp][j]);

#pragma unroll
                for (int e = 0; e < 2; e++) {
                    const int rg = r0g + rl + e;
                    const float* v = e ? hi : lo;
                    float p[8];
#pragma unroll
                    for (int j = 0; j < 8; j++) {
                        int key = k0g + ((j < 4) ? (tx * 4 + j)
                                                 : (64 + tx * 4 + j - 4));
                        p[j] = (key <= rg) ? __expf(v[j]) : 0.f;
                    }
                    float* Pp = Pout + (rowb + rg) * (size_t)TT + k0g;
                    *(float4*)(Pp + tx * 4)      = make_float4(p[0], p[1], p[2], p[3]);
                    *(float4*)(Pp + 64 + tx * 4) = make_float4(p[4], p[5], p[6], p[7]);
                    float rs = p[0] + p[1] + p[2] + p[3] + p[4] + p[5] + p[6] + p[7];
                    rs += __shfl_xor_sync(0xffffffffu, rs, 1);
                    rs += __shfl_xor_sync(0xffffffffu, rs, 2);
                    rs += __shfl_xor_sync(0xffffffffu, rs, 4);
                    rs += __shfl_xor_sync(0xffffffffu, rs, 8);
                    if (tx == 0)
                        g_Lp[(rowb + rg) * 64 + kt * 2 + ph] = rs;
                }
            }
#pragma unroll
            for (int i = 0; i < 4; i++)
#pragma unroll
                for (int j = 0; j < 8; j++) c[i][j] = 0ull;
        }
    }
#undef SLOADG
#undef QS
#undef KSD
}

// ---------------------------------------------------------------------------
// Kernel 5 (R): reduce per-tile partials -> (1/l1, lambda/l2) per row.
// ---------------------------------------------------------------------------
__global__ __launch_bounds__(256) void reduce_l()
{
    const int row  = blockIdx.x * 8 + (threadIdx.x >> 5);
    const int lane = threadIdx.x & 31;
    const int rib  = row & (TT - 1);
    const int nk   = (rib >> 7) + 1;

    float v1 = 0.f, v2 = 0.f;
    if (lane < nk) {
        v1 = g_Lp[(size_t)row * 64 + 2 * lane];
        v2 = g_Lp[(size_t)row * 64 + 2 * lane + 1];
    }
#pragma unroll
    for (int o = 16; o > 0; o >>= 1) {
        v1 += __shfl_xor_sync(0xffffffffu, v1, o);
        v2 += __shfl_xor_sync(0xffffffffu, v2, o);
    }
    if (lane == 0) {
        g_Winv[row * 2]     = 1.f / v1;
        g_Winv[row * 2 + 1] = g_lambda / v2;
    }
}

// ---------------------------------------------------------------------------
// Kernel 6 (B): PV GEMM + fused LayerNorm.  Accumulator layout SWAPPED:
// c[4 rows][4 dim-pairs]; W is broadcast (4 PACK2/kk), V read as native
// u64 dim-pairs (no dup).  Ws pad 36 (144B rows, 16B-aligned float4 reads).
// ---------------------------------------------------------------------------
__global__ __launch_bounds__(256, 2) void pv_kernel(
    float* __restrict__ out,
    const float* __restrict__ ln_gamma,
    const float* __restrict__ ln_beta)
{
    __shared__ float Ws[2][32][36];    // [buf][key][row]; reused for LN reduction
    __shared__ float Vs[2][32][260];   // [buf][key][dim]
    __shared__ float Wi2[64];          // staging scales; reused for mu/rstd

    const int b    = blockIdx.y;
    const int p    = blockIdx.x;       // 0..63
    const size_t rowb = (size_t)b * TT;

    const int tid = threadIdx.x;
    const int tx  = tid & 7;           // row group (4 rows)
    const int ty  = tid >> 3;          // dim group (8 dims)
    const int wr  = tid >> 3;          // W staging row (0..31)
    const int wkq = tid & 7;           // W staging k-quad

    float g8[8], b8[8];
#pragma unroll
    for (int k = 0; k < 8; k++) {
        g8[k] = ln_gamma[ty * 8 + k];
        b8[k] = ln_beta[ty * 8 + k];
    }

    float* redS = &Ws[0][0][0];        // [32][33] partial sums
    float* redQ = redS + 32 * 33;      // [32][33] partial sumsq (2112 <= 2304)
    float* muA  = Wi2;
    float* rsA  = Wi2 + 32;

    float4 pp1, pp2, pv4[8];

#pragma unroll 1
    for (int pass = 0; pass < 2; pass++) {
        const int r   = pass ? (127 - p) : p;
        const int t0  = r * 32;
        const int nch = r + 1;

#define PVLOAD(ch) do { \
            int kb_ = (ch) * 32; \
            size_t po_ = (rowb + t0 + wr) * (size_t)TT + kb_ + wkq * 4; \
            pp1 = *(const float4*)(g_P1 + po_); \
            pp2 = *(const float4*)(g_P2 + po_); \
            _Pragma("unroll") \
            for (int i_ = 0; i_ < 8; i_++) { \
                int idx_ = tid + i_ * 256; \
                int key_ = idx_ >> 6; \
                int dq_  = idx_ & 63; \
                pv4[i_] = *(const float4*)(g_V + (rowb + kb_ + key_) * NO + dq_ * 4); \
            } \
        } while (0)

        __syncthreads();               // previous pass fully done with smem
        if (tid < 32) {
            float2 wv = *(const float2*)(g_Winv + (rowb + t0 + tid) * 2);
            Wi2[tid * 2]     = wv.x;
            Wi2[tid * 2 + 1] = wv.y;
        }
        PVLOAD(0);

        u64 c[4][4];                   // [row][dim-pair]
#pragma unroll
        for (int i = 0; i < 4; i++)
#pragma unroll
            for (int j = 0; j < 4; j++) c[i][j] = 0ull;

        __syncthreads();               // Wi2 visible

        for (int ch = 0; ch < nch; ch++) {
            const int bf = ch & 1;
            {
                float i1  = Wi2[wr * 2];
                float li2 = Wi2[wr * 2 + 1];
                Ws[bf][wkq * 4 + 0][wr] = pp1.x * i1 - pp2.x * li2;
                Ws[bf][wkq * 4 + 1][wr] = pp1.y * i1 - pp2.y * li2;
                Ws[bf][wkq * 4 + 2][wr] = pp1.z * i1 - pp2.z * li2;
                Ws[bf][wkq * 4 + 3][wr] = pp1.w * i1 - pp2.w * li2;
            }
#pragma unroll
            for (int i = 0; i < 8; i++) {
                int idx = tid + i * 256;
                int key = idx >> 6;
                int dq  = idx & 63;
                *(float4*)(&Vs[bf][key][dq * 4]) = pv4[i];
            }
            __syncthreads();

            if (ch + 1 < nch) PVLOAD(ch + 1);

#pragma unroll 4
            for (int kk = 0; kk < 32; kk++) {
                float4 wv = *(const float4*)(&Ws[bf][kk][tx * 4]);
                ulonglong2 v0 = *(const ulonglong2*)(&Vs[bf][kk][ty * 8]);
                ulonglong2 v1 = *(const ulonglong2*)(&Vs[bf][kk][ty * 8 + 4]);
                u64 W0, W1, W2, W3;
                PACK2(W0, wv.x); PACK2(W1, wv.y); PACK2(W2, wv.z); PACK2(W3, wv.w);
                FFMA2(c[0][0], W0, v0.x); FFMA2(c[0][1], W0, v0.y);
                FFMA2(c[0][2], W0, v1.x); FFMA2(c[0][3], W0, v1.y);
                FFMA2(c[1][0], W1, v0.x); FFMA2(c[1][1], W1, v0.y);
                FFMA2(c[1][2], W1, v1.x); FFMA2(c[1][3], W1, v1.y);
                FFMA2(c[2][0], W2, v0.x); FFMA2(c[2][1], W2, v0.y);
                FFMA2(c[2][2], W2, v1.x); FFMA2(c[2][3], W2, v1.y);
                FFMA2(c[3][0], W3, v0.x); FFMA2(c[3][1], W3, v0.y);
                FFMA2(c[3][2], W3, v1.x); FFMA2(c[3][3], W3, v1.y);
            }
        }
#undef PVLOAD

        // -------- fused LayerNorm epilogue --------
        // thread owns rows t0+tx*4+r (r=0..3), dims ty*8 .. ty*8+7
        float av[4][8];
#pragma unroll
        for (int rr = 0; rr < 4; rr++)
#pragma unroll
            for (int d = 0; d < 4; d++)
                UNPACK2(av[rr][2 * d], av[rr][2 * d + 1], c[rr][d]);

        float ps[4], pqv[4];
#pragma unroll
        for (int rr = 0; rr < 4; rr++) {
            float s = 0.f, q = 0.f;
#pragma unroll
            for (int k = 0; k < 8; k++) {
                s += av[rr][k];
                q += av[rr][k] * av[rr][k];
            }
            ps[rr] = s; pqv[rr] = q;
        }

        __syncthreads();               // all compute reads of Ws done
#pragma unroll
        for (int rr = 0; rr < 4; rr++) {
            int row = tx * 4 + rr;
            redS[row * 33 + ty] = ps[rr];
            redQ[row * 33 + ty] = pqv[rr];
        }
        __syncthreads();
        if (tid < 32) {
            float s = 0.f, q = 0.f;
#pragma unroll 8
            for (int j = 0; j < 32; j++) {
                s += redS[tid * 33 + j];
                q += redQ[tid * 33 + j];
            }
            float mu = s * (1.f / 256.f);
            muA[tid] = mu;
            rsA[tid] = rsqrtf(q * (1.f / 256.f) - mu * mu + LN_EPS_F);
        }
        __syncthreads();

#pragma unroll
        for (int rr = 0; rr < 4; rr++) {
            const int row = tx * 4 + rr;
            float mu = muA[row], rs = rsA[row];
            float* o = out + (rowb + t0 + row) * NO + ty * 8;
            float4 w0, w1;
            w0.x = (av[rr][0] - mu) * rs * g8[0] + b8[0];
            w0.y = (av[rr][1] - mu) * rs * g8[1] + b8[1];
            w0.z = (av[rr][2] - mu) * rs * g8[2] + b8[2];
            w0.w = (av[rr][3] - mu) * rs * g8[3] + b8[3];
            w1.x = (av[rr][4] - mu) * rs * g8[4] + b8[4];
            w1.y = (av[rr][5] - mu) * rs * g8[5] + b8[5];
            w1.z = (av[rr][6] - mu) * rs * g8[6] + b8[6];
            w1.w = (av[rr][7] - mu) * rs * g8[7] + b8[7];
            *(float4*)(o)     = w0;
            *(float4*)(o + 4) = w1;
        }
    }
}

// ---------------------------------------------------------------------------
extern "C" void kernel_launch(void* const* d_in, const int* in_sizes, int n_in,
                              void* d_out, int out_size)
{
    const float* x   = (const float*)d_in[0];
    const float* Wq  = (const float*)d_in[1];
    const float* Wk  = (const float*)d_in[2];
    const float* Wv  = (const float*)d_in[3];
    const float* Wqs = (const float*)d_in[4];
    const float* Wks = (const float*)d_in[5];
    const float* Wvs = (const float*)d_in[6];
    const float* lq1 = (const float*)d_in[7];
    const float* lq2 = (const float*)d_in[8];
    const float* lk1 = (const float*)d_in[9];
    const float* lk2 = (const float*)d_in[10];
    const float* gam = (const float*)d_in[11];
    const float* bet = (const float*)d_in[12];

    cudaFuncSetAttribute(qkv_gemm,
                         cudaFuncAttributeMaxDynamicSharedMemorySize, QKV_SMEM);
    cudaFuncSetAttribute(score_kernel,
                         cudaFuncAttributeMaxDynamicSharedMemorySize, SC_SMEM);

    qkv_gemm<<<dim3(6, 128), 256, QKV_SMEM>>>(x, Wq, Wk, Wv);
    state_fixup<<<64, 256>>>(x, Wqs, Wks, Wvs);
    lambda_kernel<<<1, 32>>>(lq1, lq2, lk1, lk2);

    score_kernel<<<dim3(528, BB), 256, SC_SMEM>>>();
    reduce_l<<<NROW / 8, 256>>>();
    pv_kernel<<<dim3(64, BB), 256>>>((float*)d_out, gam, bet);
}

// round 17
// speedup vs baseline: 1.5639x; 1.5639x over previous
#include <cuda_runtime.h>
#include <math.h>
#include <stdint.h>

#define BB 4
#define TT 4096
#define DD 1024
#define NO 256      // 2*dv
#define NROW (BB*TT)
#define LN_EPS_F 1e-5f
#define LAMBDA_INIT 0.3555090675909693f
#define ATT_SCALE 0.0883883476483184405f   // 1/sqrt(128)

typedef unsigned long long u64;

// packed f32x2 helpers (sm_100+ PTX; SASS FFMA2/FADD2)
#define FFMA2(d, a, b) asm("fma.rn.f32x2 %0, %1, %2, %0;" : "+l"(d) : "l"(a), "l"(b))
#define PACK2(d, x)    asm("mov.b64 %0, {%1, %1};" : "=l"(d) : "r"(__float_as_uint(x)))
#define UNPACK2(lo, hi, v) do { unsigned _ul, _uh; \
    asm("mov.b64 {%0, %1}, %2;" : "=r"(_ul), "=r"(_uh) : "l"(v)); \
    (lo) = __uint_as_float(_ul); (hi) = __uint_as_float(_uh); } while (0)

// scratch (device globals: allocation-free rule)
__device__ float g_Q[NROW * NO];
__device__ float g_K[NROW * NO];
__device__ float g_V[NROW * NO];
__device__ float g_P1[67108864];     // [NROW][TT] exp-scores head 1
__device__ float g_P2[67108864];     // [NROW][TT] exp-scores head 2
__device__ float g_Lp[NROW * 64];    // per-(row, keytile, head) partial sums
__device__ float g_Winv[NROW * 2];   // (1/l1, lambda/l2) per row
__device__ float g_lambda;

// ---------------------------------------------------------------------------
// Kernel 1: uniform QKV GEMM, smem double-buffered (R15 proven version).
// ---------------------------------------------------------------------------
__global__ __launch_bounds__(256) void qkv_gemm(
    const float* __restrict__ x,
    const float* __restrict__ Wq,
    const float* __restrict__ Wk,
    const float* __restrict__ Wv)
{
    __shared__ float Xs[2][16][132];
    __shared__ float Wsm[2][16][128];

    const int nt  = blockIdx.x;
    const int mt  = blockIdx.y;
    const int mat = nt >> 1;
    const int n0  = (nt & 1) * 128;
    const float* W = (mat == 0) ? Wq : ((mat == 1) ? Wk : Wv);
    float* Out     = (mat == 0) ? g_Q : ((mat == 1) ? g_K : g_V);

    const int m0  = mt * 128;
    const int tid = threadIdx.x;
    const int tx  = tid & 15;
    const int ty  = tid >> 4;

    const int xrow = tid >> 2;
    const int xkc  = tid & 3;
    const int wkr  = tid >> 5;
    const int wnc  = tid & 31;

    const float* xp0 = x + (size_t)(m0 + xrow) * DD + xkc * 4;
    const float* xp1 = x + (size_t)(m0 + xrow + 64) * DD + xkc * 4;
    const float* wp0 = W + (size_t)wkr * NO + n0 + wnc * 4;
    const float* wp1 = W + (size_t)(wkr + 8) * NO + n0 + wnc * 4;

    u64 c[4][8];
#pragma unroll
    for (int i = 0; i < 4; i++)
#pragma unroll
        for (int j = 0; j < 8; j++) c[i][j] = 0ull;

    float4 xr0 = *(const float4*)xp0;
    float4 xr1 = *(const float4*)xp1;
    float4 wr0 = *(const float4*)wp0;
    float4 wr1 = *(const float4*)wp1;

    for (int it = 0; it < 64; it++) {
        const int bf = it & 1;
        Xs[bf][xkc * 4 + 0][xrow]      = xr0.x;
        Xs[bf][xkc * 4 + 1][xrow]      = xr0.y;
        Xs[bf][xkc * 4 + 2][xrow]      = xr0.z;
        Xs[bf][xkc * 4 + 3][xrow]      = xr0.w;
        Xs[bf][xkc * 4 + 0][xrow + 64] = xr1.x;
        Xs[bf][xkc * 4 + 1][xrow + 64] = xr1.y;
        Xs[bf][xkc * 4 + 2][xrow + 64] = xr1.z;
        Xs[bf][xkc * 4 + 3][xrow + 64] = xr1.w;
        *(float4*)(&Wsm[bf][wkr][wnc * 4])     = wr0;
        *(float4*)(&Wsm[bf][wkr + 8][wnc * 4]) = wr1;
        __syncthreads();

        if (it < 63) {
            const int k0 = (it + 1) * 16;
            xr0 = *(const float4*)(xp0 + k0);
            xr1 = *(const float4*)(xp1 + k0);
            wr0 = *(const float4*)(wp0 + (size_t)k0 * NO);
            wr1 = *(const float4*)(wp1 + (size_t)k0 * NO);
        }

#pragma unroll
        for (int kk = 0; kk < 16; kk++) {
            ulonglong2 A0 = *(const ulonglong2*)(&Xs[bf][kk][ty * 4]);
            ulonglong2 A1 = *(const ulonglong2*)(&Xs[bf][kk][64 + ty * 4]);
            float4 b0 = *(const float4*)(&Wsm[bf][kk][tx * 4]);
            float4 b1 = *(const float4*)(&Wsm[bf][kk][64 + tx * 4]);
            u64 B[8];
            PACK2(B[0], b0.x); PACK2(B[1], b0.y); PACK2(B[2], b0.z); PACK2(B[3], b0.w);
            PACK2(B[4], b1.x); PACK2(B[5], b1.y); PACK2(B[6], b1.z); PACK2(B[7], b1.w);
#pragma unroll
            for (int j = 0; j < 8; j++) {
                FFMA2(c[0][j], A0.x, B[j]);
                FFMA2(c[1][j], A0.y, B[j]);
                FFMA2(c[2][j], A1.x, B[j]);
                FFMA2(c[3][j], A1.y, B[j]);
            }
        }
    }

#pragma unroll
    for (int rp = 0; rp < 4; rp++) {
        const int r = (rp < 2) ? (ty * 4 + rp * 2) : (64 + ty * 4 + (rp - 2) * 2);
        float lo[8], hi[8];
#pragma unroll
        for (int j = 0; j < 8; j++) UNPACK2(lo[j], hi[j], c[rp][j]);
        float* o0 = Out + (size_t)(m0 + r) * NO + n0;
        float* o1 = o0 + NO;
        *(float4*)(o0 + tx * 4)      = make_float4(lo[0], lo[1], lo[2], lo[3]);
        *(float4*)(o0 + 64 + tx * 4) = make_float4(lo[4], lo[5], lo[6], lo[7]);
        *(float4*)(o1 + tx * 4)      = make_float4(hi[0], hi[1], hi[2], hi[3]);
        *(float4*)(o1 + 64 + tx * 4) = make_float4(hi[4], hi[5], hi[6], hi[7]);
    }
}

// ---------------------------------------------------------------------------
// Kernel 2: recompute the 64 state rows with the *_state weights.
// ---------------------------------------------------------------------------
__global__ __launch_bounds__(256) void state_fixup(
    const float* __restrict__ x,
    const float* __restrict__ Wqs,
    const float* __restrict__ Wks,
    const float* __restrict__ Wvs)
{
    __shared__ float xs[DD];
    const int id = blockIdx.x;
    const int b  = id >> 4;
    const int i  = id & 15;
    const int t  = (i < 8) ? i : (TT - 16 + i);
    const size_t row = (size_t)b * TT + t;
    const int tid = threadIdx.x;

    for (int d = tid; d < DD; d += 256) xs[d] = x[row * DD + d];
    __syncthreads();

    float aq = 0.f, ak = 0.f, av = 0.f;
    const int n = tid;
#pragma unroll 4
    for (int d = 0; d < DD; d++) {
        float xv = xs[d];
        aq += xv * Wqs[(size_t)d * NO + n];
        ak += xv * Wks[(size_t)d * NO + n];
        av += xv * Wvs[(size_t)d * NO + n];
    }
    g_Q[row * NO + n] = aq;
    g_K[row * NO + n] = ak;
    g_V[row * NO + n] = av;
}

// ---------------------------------------------------------------------------
// Kernel 3: lambda scalar
// ---------------------------------------------------------------------------
__global__ void lambda_kernel(const float* __restrict__ lq1,
                              const float* __restrict__ lq2,
                              const float* __restrict__ lk1,
                              const float* __restrict__ lk2)
{
    int lane = threadIdx.x;
    float s1 = 0.f, s2 = 0.f;
    for (int i = lane; i < 128; i += 32) {
        s1 += lq1[i] * lk1[i];
        s2 += lq2[i] * lk2[i];
    }
#pragma unroll
    for (int o = 16; o > 0; o >>= 1) {
        s1 += __shfl_xor_sync(0xffffffffu, s1, o);
        s2 += __shfl_xor_sync(0xffffffffu, s2, o);
    }
    if (lane == 0) g_lambda = expf(s1) - expf(s2) + LAMBDA_INIT;
}

// ---------------------------------------------------------------------------
// Kernel 4 (A): score GEMM (R15 proven version).
// ---------------------------------------------------------------------------
__global__ __launch_bounds__(256, 2) void score_kernel()
{
    __shared__ float Qs[2][16][132];
    __shared__ float Ks[2][16][132];

    const int b = blockIdx.y;
    const int t = blockIdx.x;
    int r = (int)((sqrtf(8.f * t + 1.f) - 1.f) * 0.5f);
    while ((r + 1) * (r + 2) / 2 <= t) r++;
    while (r * (r + 1) / 2 > t) r--;
    const int kt  = t - r * (r + 1) / 2;
    const int r0g = r * 128;
    const int k0g = kt * 128;
    const size_t rowb = (size_t)b * TT;

    const int tid = threadIdx.x;
    const int tx  = tid & 15;
    const int ty  = tid >> 4;
    const int sdq = tid & 3;
    const int sr0 = tid >> 2;

    const float* qb0 = g_Q + (rowb + r0g + sr0) * NO + sdq * 4;
    const float* qb1 = qb0 + (size_t)64 * NO;
    const float* kb0 = g_K + (rowb + k0g + sr0) * NO + sdq * 4;
    const float* kb1 = kb0 + (size_t)64 * NO;

    float4 pq[2], pk[2];
#define SLOADG(g) do { \
        int db_ = (((g) >> 3) * 128) + (((g) & 7) * 16); \
        pq[0] = *(const float4*)(qb0 + db_); \
        pq[1] = *(const float4*)(qb1 + db_); \
        pk[0] = *(const float4*)(kb0 + db_); \
        pk[1] = *(const float4*)(kb1 + db_); \
    } while (0)

    u64 c[4][8];
#pragma unroll
    for (int i = 0; i < 4; i++)
#pragma unroll
        for (int j = 0; j < 8; j++) c[i][j] = 0ull;

    SLOADG(0);

    for (int g = 0; g < 16; g++) {
        const int bf = g & 1;
#pragma unroll
        for (int i = 0; i < 2; i++) {
            int row = sr0 + i * 64;
            Qs[bf][sdq * 4 + 0][row] = pq[i].x * ATT_SCALE;
            Qs[bf][sdq * 4 + 1][row] = pq[i].y * ATT_SCALE;
            Qs[bf][sdq * 4 + 2][row] = pq[i].z * ATT_SCALE;
            Qs[bf][sdq * 4 + 3][row] = pq[i].w * ATT_SCALE;
            Ks[bf][sdq * 4 + 0][row] = pk[i].x;
            Ks[bf][sdq * 4 + 1][row] = pk[i].y;
            Ks[bf][sdq * 4 + 2][row] = pk[i].z;
            Ks[bf][sdq * 4 + 3][row] = pk[i].w;
        }
        __syncthreads();
        if (g < 15) SLOADG(g + 1);

#pragma unroll
        for (int kk = 0; kk < 16; kk++) {
            ulonglong2 A0 = *(const ulonglong2*)(&Qs[bf][kk][ty * 4]);
            ulonglong2 A1 = *(const ulonglong2*)(&Qs[bf][kk][64 + ty * 4]);
            float4 b0 = *(const float4*)(&Ks[bf][kk][tx * 4]);
            float4 b1 = *(const float4*)(&Ks[bf][kk][64 + tx * 4]);
            u64 B[8];
            PACK2(B[0], b0.x); PACK2(B[1], b0.y); PACK2(B[2], b0.z); PACK2(B[3], b0.w);
            PACK2(B[4], b1.x); PACK2(B[5], b1.y); PACK2(B[6], b1.z); PACK2(B[7], b1.w);
#pragma unroll
            for (int j = 0; j < 8; j++) {
                FFMA2(c[0][j], A0.x, B[j]);
                FFMA2(c[1][j], A0.y, B[j]);
                FFMA2(c[2][j], A1.x, B[j]);
                FFMA2(c[3][j], A1.y, B[j]);
            }
        }

        if ((g & 7) == 7) {
            const int ph = g >> 3;
            float* Pout = ph ? g_P2 : g_P1;
#pragma unroll
            for (int rp = 0; rp < 4; rp++) {
                const int rl = (rp < 2) ? (ty * 4 + rp * 2)
                                        : (64 + ty * 4 + (rp - 2) * 2);
                float lo[8], hi[8];
#pragma unroll
                for (int j = 0; j < 8; j++) UNPACK2(lo[j], hi[j], c[rp][j]);

#pragma unroll
                for (int e = 0; e < 2; e++) {
                    const int rg = r0g + rl + e;
                    const float* v = e ? hi : lo;
                    float p[8];
#pragma unroll
                    for (int j = 0; j < 8; j++) {
                        int key = k0g + ((j < 4) ? (tx * 4 + j)
                                                 : (64 + tx * 4 + j - 4));
                        p[j] = (key <= rg) ? __expf(v[j]) : 0.f;
                    }
                    float* Pp = Pout + (rowb + rg) * (size_t)TT + k0g;
                    *(float4*)(Pp + tx * 4)      = make_float4(p[0], p[1], p[2], p[3]);
                    *(float4*)(Pp + 64 + tx * 4) = make_float4(p[4], p[5], p[6], p[7]);
                    float rs = p[0] + p[1] + p[2] + p[3] + p[4] + p[5] + p[6] + p[7];
                    rs += __shfl_xor_sync(0xffffffffu, rs, 1);
                    rs += __shfl_xor_sync(0xffffffffu, rs, 2);
                    rs += __shfl_xor_sync(0xffffffffu, rs, 4);
                    rs += __shfl_xor_sync(0xffffffffu, rs, 8);
                    if (tx == 0)
                        g_Lp[(rowb + rg) * 64 + kt * 2 + ph] = rs;
                }
            }
#pragma unroll
            for (int i = 0; i < 4; i++)
#pragma unroll
                for (int j = 0; j < 8; j++) c[i][j] = 0ull;
        }
    }
#undef SLOADG
}

// ---------------------------------------------------------------------------
// Kernel 5 (R): reduce per-tile partials -> (1/l1, lambda/l2) per row.
// ---------------------------------------------------------------------------
__global__ __launch_bounds__(256) void reduce_l()
{
    const int row  = blockIdx.x * 8 + (threadIdx.x >> 5);
    const int lane = threadIdx.x & 31;
    const int rib  = row & (TT - 1);
    const int nk   = (rib >> 7) + 1;

    float v1 = 0.f, v2 = 0.f;
    if (lane < nk) {
        v1 = g_Lp[(size_t)row * 64 + 2 * lane];
        v2 = g_Lp[(size_t)row * 64 + 2 * lane + 1];
    }
#pragma unroll
    for (int o = 16; o > 0; o >>= 1) {
        v1 += __shfl_xor_sync(0xffffffffu, v1, o);
        v2 += __shfl_xor_sync(0xffffffffu, v2, o);
    }
    if (lane == 0) {
        g_Winv[row * 2]     = 1.f / v1;
        g_Winv[row * 2 + 1] = g_lambda / v2;
    }
}

// ---------------------------------------------------------------------------
// Kernel 6 (B): PV GEMM + fused LayerNorm.  R16 inner loop kept (swapped
// accumulator c[4 rows][4 dim-pairs], 4 PACK2/kk, native u64 V reads —
// same smem addresses/bytes as R15).  Ws pad 36 (16B-aligned float4 rows).
// ---------------------------------------------------------------------------
__global__ __launch_bounds__(256, 2) void pv_kernel(
    float* __restrict__ out,
    const float* __restrict__ ln_gamma,
    const float* __restrict__ ln_beta)
{
    __shared__ float Ws[2][32][36];    // [buf][key][row]; reused for LN reduction
    __shared__ float Vs[2][32][260];   // [buf][key][dim]
    __shared__ float Wi2[64];          // staging scales; reused for mu/rstd

    const int b    = blockIdx.y;
    const int p    = blockIdx.x;       // 0..63
    const size_t rowb = (size_t)b * TT;

    const int tid = threadIdx.x;
    const int tx  = tid & 7;           // row group (4 rows)
    const int ty  = tid >> 3;          // dim group (8 dims)
    const int wr  = tid >> 3;          // W staging row (0..31)
    const int wkq = tid & 7;           // W staging k-quad

    float g8[8], b8[8];
#pragma unroll
    for (int k = 0; k < 8; k++) {
        g8[k] = ln_gamma[ty * 8 + k];
        b8[k] = ln_beta[ty * 8 + k];
    }

    float* redS = &Ws[0][0][0];        // [32][33] partial sums
    float* redQ = redS + 32 * 33;      // [32][33] partial sumsq
    float* muA  = Wi2;
    float* rsA  = Wi2 + 32;

    float4 pp1, pp2, pv4[8];

#pragma unroll 1
    for (int pass = 0; pass < 2; pass++) {
        const int r   = pass ? (127 - p) : p;
        const int t0  = r * 32;
        const int nch = r + 1;

#define PVLOAD(ch) do { \
            int kb_ = (ch) * 32; \
            size_t po_ = (rowb + t0 + wr) * (size_t)TT + kb_ + wkq * 4; \
            pp1 = *(const float4*)(g_P1 + po_); \
            pp2 = *(const float4*)(g_P2 + po_); \
            _Pragma("unroll") \
            for (int i_ = 0; i_ < 8; i_++) { \
                int idx_ = tid + i_ * 256; \
                int key_ = idx_ >> 6; \
                int dq_  = idx_ & 63; \
                pv4[i_] = *(const float4*)(g_V + (rowb + kb_ + key_) * NO + dq_ * 4); \
            } \
        } while (0)

        __syncthreads();               // previous pass fully done with smem
        if (tid < 32) {
            float2 wv = *(const float2*)(g_Winv + (rowb + t0 + tid) * 2);
            Wi2[tid * 2]     = wv.x;
            Wi2[tid * 2 + 1] = wv.y;
        }
        PVLOAD(0);

        u64 c[4][4];                   // [row][dim-pair]
#pragma unroll
        for (int i = 0; i < 4; i++)
#pragma unroll
            for (int j = 0; j < 4; j++) c[i][j] = 0ull;

        __syncthreads();               // Wi2 visible

        for (int ch = 0; ch < nch; ch++) {
            const int bf = ch & 1;
            {
                float i1  = Wi2[wr * 2];
                float li2 = Wi2[wr * 2 + 1];
                Ws[bf][wkq * 4 + 0][wr] = pp1.x * i1 - pp2.x * li2;
                Ws[bf][wkq * 4 + 1][wr] = pp1.y * i1 - pp2.y * li2;
                Ws[bf][wkq * 4 + 2][wr] = pp1.z * i1 - pp2.z * li2;
                Ws[bf][wkq * 4 + 3][wr] = pp1.w * i1 - pp2.w * li2;
            }
#pragma unroll
            for (int i = 0; i < 8; i++) {
                int idx = tid + i * 256;
                int key = idx >> 6;
                int dq  = idx & 63;
                *(float4*)(&Vs[bf][key][dq * 4]) = pv4[i];
            }
            __syncthreads();

            if (ch + 1 < nch) PVLOAD(ch + 1);

#pragma unroll 4
            for (int kk = 0; kk < 32; kk++) {
                float4 wv = *(const float4*)(&Ws[bf][kk][tx * 4]);
                ulonglong2 v0 = *(const ulonglong2*)(&Vs[bf][kk][ty * 8]);
                ulonglong2 v1 = *(const ulonglong2*)(&Vs[bf][kk][ty * 8 + 4]);
                u64 W0, W1, W2, W3;
                PACK2(W0, wv.x); PACK2(W1, wv.y); PACK2(W2, wv.z); PACK2(W3, wv.w);
                FFMA2(c[0][0], W0, v0.x); FFMA2(c[0][1], W0, v0.y);
                FFMA2(c[0][2], W0, v1.x); FFMA2(c[0][3], W0, v1.y);
                FFMA2(c[1][0], W1, v0.x); FFMA2(c[1][1], W1, v0.y);
                FFMA2(c[1][2], W1, v1.x); FFMA2(c[1][3], W1, v1.y);
                FFMA2(c[2][0], W2, v0.x); FFMA2(c[2][1], W2, v0.y);
                FFMA2(c[2][2], W2, v1.x); FFMA2(c[2][3], W2, v1.y);
                FFMA2(c[3][0], W3, v0.x); FFMA2(c[3][1], W3, v0.y);
                FFMA2(c[3][2], W3, v1.x); FFMA2(c[3][3], W3, v1.y);
            }
        }
#undef PVLOAD

        // -------- fused LayerNorm epilogue --------
        float av[4][8];
#pragma unroll
        for (int rr = 0; rr < 4; rr++)
#pragma unroll
            for (int d = 0; d < 4; d++)
                UNPACK2(av[rr][2 * d], av[rr][2 * d + 1], c[rr][d]);

        float ps[4], pqv[4];
#pragma unroll
        for (int rr = 0; rr < 4; rr++) {
            float s = 0.f, q = 0.f;
#pragma unroll
            for (int k = 0; k < 8; k++) {
                s += av[rr][k];
                q += av[rr][k] * av[rr][k];
            }
            ps[rr] = s; pqv[rr] = q;
        }

        __syncthreads();               // all compute reads of Ws done
#pragma unroll
        for (int rr = 0; rr < 4; rr++) {
            int row = tx * 4 + rr;
            redS[row * 33 + ty] = ps[rr];
            redQ[row * 33 + ty] = pqv[rr];
        }
        __syncthreads();
        if (tid < 32) {
            float s = 0.f, q = 0.f;
#pragma unroll 8
            for (int j = 0; j < 32; j++) {
                s += redS[tid * 33 + j];
                q += redQ[tid * 33 + j];
            }
            float mu = s * (1.f / 256.f);
            muA[tid] = mu;
            rsA[tid] = rsqrtf(q * (1.f / 256.f) - mu * mu + LN_EPS_F);
        }
        __syncthreads();

#pragma unroll
        for (int rr = 0; rr < 4; rr++) {
            const int row = tx * 4 + rr;
            float mu = muA[row], rs = rsA[row];
            float* o = out + (rowb + t0 + row) * NO + ty * 8;
            float4 w0, w1;
            w0.x = (av[rr][0] - mu) * rs * g8[0] + b8[0];
            w0.y = (av[rr][1] - mu) * rs * g8[1] + b8[1];
            w0.z = (av[rr][2] - mu) * rs * g8[2] + b8[2];
            w0.w = (av[rr][3] - mu) * rs * g8[3] + b8[3];
            w1.x = (av[rr][4] - mu) * rs * g8[4] + b8[4];
            w1.y = (av[rr][5] - mu) * rs * g8[5] + b8[5];
            w1.z = (av[rr][6] - mu) * rs * g8[6] + b8[6];
            w1.w = (av[rr][7] - mu) * rs * g8[7] + b8[7];
            *(float4*)(o)     = w0;
            *(float4*)(o + 4) = w1;
        }
    }
}

// ---------------------------------------------------------------------------
extern "C" void kernel_launch(void* const* d_in, const int* in_sizes, int n_in,
                              void* d_out, int out_size)
{
    const float* x   = (const float*)d_in[0];
    const float* Wq  = (const float*)d_in[1];
    const float* Wk  = (const float*)d_in[2];
    const float* Wv  = (const float*)d_in[3];
    const float* Wqs = (const float*)d_in[4];
    const float* Wks = (const float*)d_in[5];
    const float* Wvs = (const float*)d_in[6];
    const float* lq1 = (const float*)d_in[7];
    const float* lq2 = (const float*)d_in[8];
    const float* lk1 = (const float*)d_in[9];
    const float* lk2 = (const float*)d_in[10];
    const float* gam = (const float*)d_in[11];
    const float* bet = (const float*)d_in[12];

    qkv_gemm<<<dim3(6, 128), 256>>>(x, Wq, Wk, Wv);
    state_fixup<<<64, 256>>>(x, Wqs, Wks, Wvs);
    lambda_kernel<<<1, 32>>>(lq1, lq2, lk1, lk2);

    score_kernel<<<dim3(528, BB), 256>>>();
    reduce_l<<<NROW / 8, 256>>>();
    pv_kernel<<<dim3(64, BB), 256>>>((float*)d_out, gam, bet);
}